// round 11
// baseline (speedup 1.0000x reference)
#include <cuda_runtime.h>
#include <cuda_fp16.h>
#include <mma.h>

using namespace nvcuda;

#define N_NODES 100000
#define N_EDGES 1600000
#define DIN 128
#define DHID 256
#define DOUT 64
#define SLOTS 64                     // padded bucket width (P(deg>64) ~ e^-126)

// Static scratch (no runtime allocation allowed). Zero-initialized at load.
__device__ __align__(16) __half g_zh [(size_t)N_NODES * DOUT];  // z  (fp16)
__device__ __align__(16) __half g_z1h[(size_t)N_NODES * DOUT];  // z1 (fp16)
__device__ __align__(16) __half g_wfh[DIN * DOUT];              // Wf (fp16)
__device__ int   g_cnt[N_NODES];                     // fill cursor == degree;
                                                     // reset by gather2
__device__ int   g_csr_src[(size_t)N_NODES * SLOTS]; // src ids, bucketed by dst

// ---------------------------------------------------------------------------
// Launch 1: Wf = W1 @ W2 (fp32 compute, fp16 store). 128 blocks x 256 thr.
// ---------------------------------------------------------------------------
__global__ void prep_kernel(const float* __restrict__ W1,
                            const float* __restrict__ W2) {
    __shared__ float red[4][64];
    int i  = blockIdx.x;
    int j  = threadIdx.x & 63;
    int ks = threadIdx.x >> 6;           // 0..3
    float acc = 0.f;
#pragma unroll 8
    for (int k = ks * 64; k < ks * 64 + 64; ++k)
        acc += W1[i * DHID + k] * W2[k * DOUT + j];
    red[ks][j] = acc;
    __syncthreads();
    if (ks == 0)
        g_wfh[i * DOUT + j] =
            __float2half_rn(red[0][j] + red[1][j] + red[2][j] + red[3][j]);
}

// ---------------------------------------------------------------------------
// Launch 2 (combined): blocks [0, GEMM_B)        -> wmma GEMM (fp16->fp32acc)
//                      blocks [GEMM_B, +FILL_B)  -> bucket fill (int4 edges)
// ---------------------------------------------------------------------------
#define GTILE 64
#define THR 128
#define GEMM_B ((N_NODES + GTILE - 1) / GTILE)       // 1563
#define FILL_B 2048
#define A_LD (DIN + 8)                               // 136 halves

__device__ __forceinline__ void do_fill(int bid,
                                        const int* __restrict__ es,
                                        const int* __restrict__ ed) {
    const int4* es4 = (const int4*)es;
    const int4* ed4 = (const int4*)ed;
    const int n4 = N_EDGES / 4;
    int i = bid * THR + threadIdx.x;
    int stride = FILL_B * THR;
    for (; i < n4; i += stride) {
        int4 sv = __ldg(es4 + i);
        int4 dv = __ldg(ed4 + i);
#pragma unroll
        for (int j = 0; j < 4; ++j) {
            int s = (&sv.x)[j];
            int d = (&dv.x)[j];
            if ((unsigned)s >= N_NODES || (unsigned)d >= N_NODES) continue;
            int pos = atomicAdd(&g_cnt[d], 1);
            if (pos < SLOTS) g_csr_src[(size_t)d * SLOTS + pos] = s;
        }
    }
}

// wmma GEMM: 64 nodes x 64 cols per block; 4 warps x (16 rows x 4 col-frags).
__device__ __forceinline__ void do_gemm(int bid, const float* __restrict__ x,
                                        __half* As_raw, __half* Bs_raw) {
    __half (*As)[A_LD] = (__half (*)[A_LD])As_raw;   // 64 x 136 = 17408 B
    __half (*Bs)[DOUT] = (__half (*)[DOUT])Bs_raw;   // 128 x 64 = 16384 B
    int tid  = threadIdx.x;
    int warp = tid >> 5;
    int node0 = bid * GTILE;

    // Load B (Wf fp16): 16384 B = 1024 uint4, 8 per thread.
    {
        const uint4* src = (const uint4*)g_wfh;
        uint4* dst = (uint4*)&Bs[0][0];
#pragma unroll
        for (int r = 0; r < 8; ++r)
            dst[r * THR + tid] = __ldg(src + r * THR + tid);
    }
    // Load A: 64 rows x 128 fp32 -> fp16 smem. 2 threads per row.
    {
        int row   = tid >> 1;
        int half_ = tid & 1;
        int node  = node0 + row;
        __half2* dst = (__half2*)&As[row][half_ * 64];
        if (node < N_NODES) {
            const float4* xr = (const float4*)(x + (size_t)node * DIN) + half_ * 16;
#pragma unroll
            for (int q = 0; q < 16; ++q) {
                float4 v = __ldg(xr + q);
                dst[q * 2]     = __floats2half2_rn(v.x, v.y);
                dst[q * 2 + 1] = __floats2half2_rn(v.z, v.w);
            }
        } else {
            __half2 zz = __float2half2_rn(0.f);
#pragma unroll
            for (int q = 0; q < 32; ++q) dst[q] = zz;
        }
    }
    __syncthreads();

    wmma::fragment<wmma::accumulator, 16, 16, 16, float> acc[4];
#pragma unroll
    for (int c = 0; c < 4; ++c) wmma::fill_fragment(acc[c], 0.f);

#pragma unroll
    for (int k = 0; k < DIN / 16; ++k) {
        wmma::fragment<wmma::matrix_a, 16, 16, 16, __half, wmma::row_major> a;
        wmma::load_matrix_sync(a, &As[warp * 16][k * 16], A_LD);
#pragma unroll
        for (int c = 0; c < 4; ++c) {
            wmma::fragment<wmma::matrix_b, 16, 16, 16, __half, wmma::row_major> b;
            wmma::load_matrix_sync(b, &Bs[k * 16][c * 16], DOUT);
            wmma::mma_sync(acc[c], a, b, acc[c]);
        }
    }
    __syncthreads();                       // done reading As; reuse as C stage

    float* Cs = (float*)&As[0][0];         // 64 x 64 fp32 = 16384 B (fits)
#pragma unroll
    for (int c = 0; c < 4; ++c)
        wmma::store_matrix_sync(Cs + warp * 16 * 64 + c * 16, acc[c], 64,
                                wmma::mem_row_major);
    __syncthreads();

    // Convert + write: 4096 fp32 -> 512 uint4 of halves, 4 per thread.
    uint4* zh4 = (uint4*)g_zh;
#pragma unroll
    for (int r = 0; r < 4; ++r) {
        int idx  = r * THR + tid;          // 0..511
        int row  = idx >> 3;
        int col8 = idx & 7;
        int node = node0 + row;
        if (node < N_NODES) {
            const float* cp = Cs + row * 64 + col8 * 8;
            uint4 o;
            unsigned* op = &o.x;
#pragma unroll
            for (int j = 0; j < 4; ++j) {
                __half2 h = __floats2half2_rn(cp[2 * j], cp[2 * j + 1]);
                op[j] = *reinterpret_cast<unsigned*>(&h);
            }
            zh4[(size_t)node * 8 + col8] = o;
        }
    }
}

__global__ void __launch_bounds__(THR)
fill_gemm_kernel(const int* __restrict__ es,
                 const int* __restrict__ ed,
                 const float* __restrict__ x) {
    __shared__ __half As_raw[GTILE * A_LD];   // 17408 B
    __shared__ __half Bs_raw[DIN * DOUT];     // 16384 B
    if (blockIdx.x < GEMM_B) do_gemm(blockIdx.x, x, As_raw, Bs_raw);
    else                     do_fill(blockIdx.x - GEMM_B, es, ed);
}

// ---------------------------------------------------------------------------
// Gather on fp16 rows: 8 lanes per node, lane owns one uint4 (8 halves).
// One 128B L2 line per edge row. Accumulate fp32; unroll-8 MLP.
// WRITE_HALF: output fp16 (layer 1).  RESET: zero counters (layer 2).
// ---------------------------------------------------------------------------
__device__ __forceinline__ void acc_add(float* acc, uint4 v) {
    const __half2* h = reinterpret_cast<const __half2*>(&v);
#pragma unroll
    for (int j = 0; j < 4; ++j) {
        float2 f = __half22float2(h[j]);
        acc[2 * j]     += f.x;
        acc[2 * j + 1] += f.y;
    }
}

template <bool WRITE_HALF, bool RESET>
__global__ void gather_h_kernel(const uint4* __restrict__ feat_h,
                                void* __restrict__ outp) {
    int t = blockIdx.x * blockDim.x + threadIdx.x;
    int node = t >> 3;                 // four nodes per warp
    int l8   = t & 7;
    if (node >= N_NODES) return;

    int deg = __ldg(&g_cnt[node]);
    if (deg > SLOTS) deg = SLOTS;
    const int* bucket = g_csr_src + (size_t)node * SLOTS;

    float acc[8] = {0.f, 0.f, 0.f, 0.f, 0.f, 0.f, 0.f, 0.f};
    acc_add(acc, __ldg(&feat_h[(size_t)node * 8 + l8]));   // self term

    int i = 0;
    for (; i + 8 <= deg; i += 8) {
        int s[8];
#pragma unroll
        for (int j = 0; j < 8; ++j) s[j] = __ldg(bucket + i + j);
        uint4 v[8];
#pragma unroll
        for (int j = 0; j < 8; ++j) v[j] = __ldg(&feat_h[(size_t)s[j] * 8 + l8]);
#pragma unroll
        for (int j = 0; j < 8; ++j) acc_add(acc, v[j]);
    }
    for (; i < deg; ++i) {
        int s = __ldg(bucket + i);
        acc_add(acc, __ldg(&feat_h[(size_t)s * 8 + l8]));
    }

    if (WRITE_HALF) {
        uint4 o;
        unsigned* op = &o.x;
#pragma unroll
        for (int j = 0; j < 4; ++j) {
            __half2 h = __floats2half2_rn(acc[2 * j], acc[2 * j + 1]);
            op[j] = *reinterpret_cast<unsigned*>(&h);
        }
        ((uint4*)outp)[(size_t)node * 8 + l8] = o;
    } else {
        float4 a = make_float4(acc[0], acc[1], acc[2], acc[3]);
        float4 b = make_float4(acc[4], acc[5], acc[6], acc[7]);
        ((float4*)outp)[(size_t)node * 16 + l8 * 2]     = a;
        ((float4*)outp)[(size_t)node * 16 + l8 * 2 + 1] = b;
    }
    if (RESET && l8 == 0) g_cnt[node] = 0;   // clean for the next call
}

// ---------------------------------------------------------------------------
extern "C" void kernel_launch(void* const* d_in, const int* in_sizes, int n_in,
                              void* d_out, int out_size) {
    const float* x  = (const float*)d_in[0];
    const int*   es = (const int*)d_in[1];
    const int*   ed = (const int*)d_in[2];
    const float* W1 = (const float*)d_in[3];
    const float* W2 = (const float*)d_in[4];
    float*       out = (float*)d_out;

    void *p_zh, *p_z1h;
    cudaGetSymbolAddress(&p_zh,  g_zh);
    cudaGetSymbolAddress(&p_z1h, g_z1h);
    const uint4* zh  = (const uint4*)p_zh;
    uint4*       z1h = (uint4*)p_z1h;

    const int gather_blocks = (N_NODES * 8 + 255) / 256;   // 3125

    prep_kernel<<<DIN, 256>>>(W1, W2);                       // Wf (fp16)
    fill_gemm_kernel<<<GEMM_B + FILL_B, THR>>>(es, ed, x);   // GEMM ∥ buckets
    gather_h_kernel<true,  false><<<gather_blocks, 256>>>(zh, (void*)z1h);
    gather_h_kernel<false, true ><<<gather_blocks, 256>>>((const uint4*)z1h, (void*)out);
}

// round 12
// speedup vs baseline: 1.0390x; 1.0390x over previous
#include <cuda_runtime.h>
#include <cuda_fp16.h>

#define N_NODES 100000
#define N_EDGES 1600000
#define DIN 128
#define DHID 256
#define DOUT 64
#define SLOTS 64                     // padded bucket width (P(deg>64) ~ e^-126)

// Static scratch (no runtime allocation allowed). Zero-initialized at load.
__device__ __align__(16) __half g_zh [(size_t)N_NODES * DOUT];  // z  (fp16)
__device__ __align__(16) __half g_z1h[(size_t)N_NODES * DOUT];  // z1 (fp16)
__device__ float g_wf[DIN * DOUT];                   // fused W1 @ W2 (fp32)
__device__ int   g_cnt[N_NODES];                     // fill cursor == degree;
                                                     // reset by gather2
__device__ int   g_csr_src[(size_t)N_NODES * SLOTS]; // src ids, bucketed by dst

// ---------------------------------------------------------------------------
// Launch 1: Wf = W1 @ W2 (fp32). 128 blocks x 256 threads, 4-way k-split.
// ---------------------------------------------------------------------------
__global__ void prep_kernel(const float* __restrict__ W1,
                            const float* __restrict__ W2) {
    __shared__ float red[4][64];
    int i  = blockIdx.x;
    int j  = threadIdx.x & 63;
    int ks = threadIdx.x >> 6;           // 0..3
    float acc = 0.f;
#pragma unroll 8
    for (int k = ks * 64; k < ks * 64 + 64; ++k)
        acc += W1[i * DHID + k] * W2[k * DOUT + j];
    red[ks][j] = acc;
    __syncthreads();
    if (ks == 0)
        g_wf[i * DOUT + j] = red[0][j] + red[1][j] + red[2][j] + red[3][j];
}

// ---------------------------------------------------------------------------
// Launch 2 (combined): blocks [0, GEMM_B)        -> register-tiled f32x2 GEMM
//                      blocks [GEMM_B, +FILL_B)  -> bucket fill (int4 edges)
// KC=16 keeps static smem at 12.4 KB so fill blocks keep full occupancy.
// ---------------------------------------------------------------------------
#define TILE_N 128
#define KC 16
#define THR 128
#define GEMM_B ((N_NODES + TILE_N - 1) / TILE_N)     // 782
#define FILL_B 2048
#define XT_STRIDE 132

__device__ __forceinline__ void do_fill(int bid,
                                        const int* __restrict__ es,
                                        const int* __restrict__ ed) {
    const int4* es4 = (const int4*)es;
    const int4* ed4 = (const int4*)ed;
    const int n4 = N_EDGES / 4;
    int i = bid * THR + threadIdx.x;
    int stride = FILL_B * THR;
    for (; i < n4; i += stride) {
        int4 sv = __ldg(es4 + i);
        int4 dv = __ldg(ed4 + i);
#pragma unroll
        for (int j = 0; j < 4; ++j) {
            int s = (&sv.x)[j];
            int d = (&dv.x)[j];
            if ((unsigned)s >= N_NODES || (unsigned)d >= N_NODES) continue;
            int pos = atomicAdd(&g_cnt[d], 1);
            if (pos < SLOTS) g_csr_src[(size_t)d * SLOTS + pos] = s;
        }
    }
}

// Register-tiled GEMM: 128 nodes x 64 cols per block; thread = 8n x 8c.
// Epilogue converts to fp16 rows in g_zh.
__device__ __forceinline__ void do_gemm(int bid, const float* __restrict__ x,
                                        float* ws_c, float* xt) {
    int tid = threadIdx.x;
    int tc = tid & 7;                        // cols 8*tc .. 8*tc+7
    int tn = tid >> 3;                       // nodes 8*tn .. 8*tn+7
    int node0 = bid * TILE_N;

    unsigned long long acc[8][4];
#pragma unroll
    for (int i = 0; i < 8; ++i)
#pragma unroll
        for (int j = 0; j < 4; ++j) acc[i][j] = 0ull;

    for (int kc = 0; kc < DIN; kc += KC) {
        // ws chunk: KC*64 = 1024 floats = 256 float4, 2 per thread.
#pragma unroll
        for (int r = 0; r < 2; ++r) {
            int i = r * THR + tid;
            ((float4*)ws_c)[i] = __ldg(&((const float4*)g_wf)[(kc * DOUT) / 4 + i]);
        }
        // xt chunk: 128 nodes x KC k transposed. 512 float4, 4 per thread.
#pragma unroll
        for (int r = 0; r < 4; ++r) {
            int idx = r * THR + tid;
            int n  = idx >> 2;               // 0..127
            int k4 = idx & 3;
            int node = node0 + n;
            float4 v = (node < N_NODES)
                ? __ldg(&((const float4*)x)[(size_t)node * (DIN / 4) + (kc >> 2) + k4])
                : make_float4(0.f, 0.f, 0.f, 0.f);
            xt[(k4 * 4 + 0) * XT_STRIDE + n] = v.x;
            xt[(k4 * 4 + 1) * XT_STRIDE + n] = v.y;
            xt[(k4 * 4 + 2) * XT_STRIDE + n] = v.z;
            xt[(k4 * 4 + 3) * XT_STRIDE + n] = v.w;
        }
        __syncthreads();

#pragma unroll 4
        for (int k = 0; k < KC; ++k) {
            float4 xa = *(const float4*)(xt + k * XT_STRIDE + tn * 8);
            float4 xb = *(const float4*)(xt + k * XT_STRIDE + tn * 8 + 4);
            ulonglong2 w01 = *(const ulonglong2*)(ws_c + k * DOUT + tc * 8);
            ulonglong2 w23 = *(const ulonglong2*)(ws_c + k * DOUT + tc * 8 + 4);
            float xv[8] = {xa.x, xa.y, xa.z, xa.w, xb.x, xb.y, xb.z, xb.w};
#pragma unroll
            for (int i = 0; i < 8; ++i) {
                unsigned long long x2;
                asm("mov.b64 %0, {%1, %1};" : "=l"(x2) : "f"(xv[i]));
                asm("fma.rn.f32x2 %0, %1, %2, %0;" : "+l"(acc[i][0]) : "l"(x2), "l"(w01.x));
                asm("fma.rn.f32x2 %0, %1, %2, %0;" : "+l"(acc[i][1]) : "l"(x2), "l"(w01.y));
                asm("fma.rn.f32x2 %0, %1, %2, %0;" : "+l"(acc[i][2]) : "l"(x2), "l"(w23.x));
                asm("fma.rn.f32x2 %0, %1, %2, %0;" : "+l"(acc[i][3]) : "l"(x2), "l"(w23.y));
            }
        }
        __syncthreads();
    }

    uint4* zh4 = (uint4*)g_zh;               // 8 uint4 per node row
#pragma unroll
    for (int i = 0; i < 8; ++i) {
        int node = node0 + tn * 8 + i;
        if (node < N_NODES) {
            uint4 o;
            unsigned* op = &o.x;
#pragma unroll
            for (int j = 0; j < 4; ++j) {
                unsigned long long a = acc[i][j];
                float lo = __uint_as_float((unsigned)a);
                float hi = __uint_as_float((unsigned)(a >> 32));
                __half2 h = __floats2half2_rn(lo, hi);
                op[j] = *reinterpret_cast<unsigned*>(&h);
            }
            zh4[(size_t)node * 8 + tc] = o;
        }
    }
}

__global__ void __launch_bounds__(THR)
fill_gemm_kernel(const int* __restrict__ es,
                 const int* __restrict__ ed,
                 const float* __restrict__ x) {
    __shared__ float ws_c[KC * DOUT];        // 4 KB
    __shared__ float xt[KC * XT_STRIDE];     // 8.4 KB
    if (blockIdx.x < GEMM_B) do_gemm(blockIdx.x, x, ws_c, xt);
    else                     do_fill(blockIdx.x - GEMM_B, es, ed);
}

// ---------------------------------------------------------------------------
// Gather, warp-per-node (no intra-warp divergence): lane = (edge-group eg,
// col-chunk l8). Warp processes 4 edges per converged iteration, unroll x2.
// End: butterfly shuffle (xor 8, 16) sums the 4 edge-groups; lanes 0-7 write.
// Accumulation fp32. WRITE_HALF: fp16 out (layer 1). RESET: zero counters.
// ---------------------------------------------------------------------------
__device__ __forceinline__ void acc_add(float* acc, uint4 v) {
    const __half2* h = reinterpret_cast<const __half2*>(&v);
#pragma unroll
    for (int j = 0; j < 4; ++j) {
        float2 f = __half22float2(h[j]);
        acc[2 * j]     += f.x;
        acc[2 * j + 1] += f.y;
    }
}

template <bool WRITE_HALF, bool RESET>
__global__ void gather_h_kernel(const uint4* __restrict__ feat_h,
                                void* __restrict__ outp) {
    int t = blockIdx.x * blockDim.x + threadIdx.x;
    int node = t >> 5;                 // one warp per node
    int lane = t & 31;
    int eg   = lane >> 3;              // edge group 0..3
    int l8   = lane & 7;               // col chunk 0..7
    if (node >= N_NODES) return;

    int deg = __ldg(&g_cnt[node]);
    if (deg > SLOTS) deg = SLOTS;
    const int* bucket = g_csr_src + (size_t)node * SLOTS;

    float acc[8] = {0.f, 0.f, 0.f, 0.f, 0.f, 0.f, 0.f, 0.f};
    if (eg == 0)
        acc_add(acc, __ldg(&feat_h[(size_t)node * 8 + l8]));   // self term

    int i = 0;
    for (; i + 8 <= deg; i += 8) {                 // 8 edges per iteration
        int s0 = __ldg(bucket + i + eg);
        int s1 = __ldg(bucket + i + 4 + eg);
        uint4 v0 = __ldg(&feat_h[(size_t)s0 * 8 + l8]);
        uint4 v1 = __ldg(&feat_h[(size_t)s1 * 8 + l8]);
        acc_add(acc, v0);
        acc_add(acc, v1);
    }
    if (i + 4 <= deg) {                            // 4-edge step
        int s0 = __ldg(bucket + i + eg);
        acc_add(acc, __ldg(&feat_h[(size_t)s0 * 8 + l8]));
        i += 4;
    }
    int rem = deg - i;                             // 0..3
    if (eg < rem) {
        int s0 = __ldg(bucket + i + eg);
        acc_add(acc, __ldg(&feat_h[(size_t)s0 * 8 + l8]));
    }

    // Reduce across the 4 edge groups (lanes l8, l8+8, l8+16, l8+24).
#pragma unroll
    for (int j = 0; j < 8; ++j) {
        acc[j] += __shfl_xor_sync(0xffffffffu, acc[j], 8);
        acc[j] += __shfl_xor_sync(0xffffffffu, acc[j], 16);
    }

    if (lane < 8) {
        if (WRITE_HALF) {
            uint4 o;
            unsigned* op = &o.x;
#pragma unroll
            for (int j = 0; j < 4; ++j) {
                __half2 h = __floats2half2_rn(acc[2 * j], acc[2 * j + 1]);
                op[j] = *reinterpret_cast<unsigned*>(&h);
            }
            ((uint4*)outp)[(size_t)node * 8 + l8] = o;
        } else {
            float4 a = make_float4(acc[0], acc[1], acc[2], acc[3]);
            float4 b = make_float4(acc[4], acc[5], acc[6], acc[7]);
            ((float4*)outp)[(size_t)node * 16 + l8 * 2]     = a;
            ((float4*)outp)[(size_t)node * 16 + l8 * 2 + 1] = b;
        }
    }
    if (RESET && lane == 0) g_cnt[node] = 0;   // clean for the next call
}

// ---------------------------------------------------------------------------
extern "C" void kernel_launch(void* const* d_in, const int* in_sizes, int n_in,
                              void* d_out, int out_size) {
    const float* x  = (const float*)d_in[0];
    const int*   es = (const int*)d_in[1];
    const int*   ed = (const int*)d_in[2];
    const float* W1 = (const float*)d_in[3];
    const float* W2 = (const float*)d_in[4];
    float*       out = (float*)d_out;

    void *p_zh, *p_z1h;
    cudaGetSymbolAddress(&p_zh,  g_zh);
    cudaGetSymbolAddress(&p_z1h, g_z1h);
    const uint4* zh  = (const uint4*)p_zh;
    uint4*       z1h = (uint4*)p_z1h;

    const int gather_blocks = (N_NODES * 32 + 255) / 256;   // 12500

    prep_kernel<<<DIN, 256>>>(W1, W2);                       // Wf
    fill_gemm_kernel<<<GEMM_B + FILL_B, THR>>>(es, ed, x);   // GEMM ∥ buckets
    gather_h_kernel<true,  false><<<gather_blocks, 256>>>(zh, (void*)z1h);
    gather_h_kernel<false, true ><<<gather_blocks, 256>>>((const uint4*)z1h, (void*)out);
}

// round 13
// speedup vs baseline: 1.1872x; 1.1426x over previous
#include <cuda_runtime.h>
#include <cuda_fp16.h>

#define N_NODES 100000
#define N_EDGES 1600000
#define DIN 128
#define DHID 256
#define DOUT 64
#define SLOTS 64                     // padded bucket width (P(deg>64) ~ e^-126)

// Static scratch (no runtime allocation allowed). Zero-initialized at load.
__device__ __align__(16) __half g_zh [(size_t)N_NODES * DOUT];  // z  (fp16)
__device__ __align__(16) __half g_z1h[(size_t)N_NODES * DOUT];  // z1 (fp16)
__device__ float g_wf[DIN * DOUT];                   // fused W1 @ W2 (fp32)
__device__ int   g_cnt[N_NODES];                     // fill cursor == degree;
                                                     // reset by gather2
__device__ int   g_csr_src[(size_t)N_NODES * SLOTS]; // src ids, bucketed by dst

// ---------------------------------------------------------------------------
// Launch 1: Wf = W1 @ W2 (fp32). 128 blocks x 256 threads, 4-way k-split.
// ---------------------------------------------------------------------------
__global__ void prep_kernel(const float* __restrict__ W1,
                            const float* __restrict__ W2) {
    __shared__ float red[4][64];
    int i  = blockIdx.x;
    int j  = threadIdx.x & 63;
    int ks = threadIdx.x >> 6;           // 0..3
    float acc = 0.f;
#pragma unroll 8
    for (int k = ks * 64; k < ks * 64 + 64; ++k)
        acc += W1[i * DHID + k] * W2[k * DOUT + j];
    red[ks][j] = acc;
    __syncthreads();
    if (ks == 0)
        g_wf[i * DOUT + j] = red[0][j] + red[1][j] + red[2][j] + red[3][j];
}

// ---------------------------------------------------------------------------
// Launch 2 (combined): blocks [0, GEMM_B)        -> register-tiled f32x2 GEMM
//                      blocks [GEMM_B, +FILL_B)  -> bucket fill (int4 edges)
// KC=16 keeps static smem at 12.4 KB so fill blocks keep high occupancy.
// ---------------------------------------------------------------------------
#define TILE_N 128
#define KC 16
#define THR 128
#define GEMM_B ((N_NODES + TILE_N - 1) / TILE_N)     // 782
#define FILL_B 2048
#define XT_STRIDE 132

__device__ __forceinline__ void do_fill(int bid,
                                        const int* __restrict__ es,
                                        const int* __restrict__ ed) {
    const int4* es4 = (const int4*)es;
    const int4* ed4 = (const int4*)ed;
    const int n4 = N_EDGES / 4;
    int i = bid * THR + threadIdx.x;
    int stride = FILL_B * THR;
    for (; i < n4; i += stride) {
        int4 sv = __ldg(es4 + i);
        int4 dv = __ldg(ed4 + i);
#pragma unroll
        for (int j = 0; j < 4; ++j) {
            int s = (&sv.x)[j];
            int d = (&dv.x)[j];
            if ((unsigned)s >= N_NODES || (unsigned)d >= N_NODES) continue;
            int pos = atomicAdd(&g_cnt[d], 1);
            if (pos < SLOTS) g_csr_src[(size_t)d * SLOTS + pos] = s;
        }
    }
}

// Register-tiled GEMM: 128 nodes x 64 cols per block; thread = 8n x 8c.
// Epilogue converts to fp16 rows in g_zh.
__device__ __forceinline__ void do_gemm(int bid, const float* __restrict__ x,
                                        float* ws_c, float* xt) {
    int tid = threadIdx.x;
    int tc = tid & 7;                        // cols 8*tc .. 8*tc+7
    int tn = tid >> 3;                       // nodes 8*tn .. 8*tn+7
    int node0 = bid * TILE_N;

    unsigned long long acc[8][4];
#pragma unroll
    for (int i = 0; i < 8; ++i)
#pragma unroll
        for (int j = 0; j < 4; ++j) acc[i][j] = 0ull;

    for (int kc = 0; kc < DIN; kc += KC) {
        // ws chunk: KC*64 = 1024 floats = 256 float4, 2 per thread.
#pragma unroll
        for (int r = 0; r < 2; ++r) {
            int i = r * THR + tid;
            ((float4*)ws_c)[i] = __ldg(&((const float4*)g_wf)[(kc * DOUT) / 4 + i]);
        }
        // xt chunk: 128 nodes x KC k transposed. 512 float4, 4 per thread.
#pragma unroll
        for (int r = 0; r < 4; ++r) {
            int idx = r * THR + tid;
            int n  = idx >> 2;               // 0..127
            int k4 = idx & 3;
            int node = node0 + n;
            float4 v = (node < N_NODES)
                ? __ldg(&((const float4*)x)[(size_t)node * (DIN / 4) + (kc >> 2) + k4])
                : make_float4(0.f, 0.f, 0.f, 0.f);
            xt[(k4 * 4 + 0) * XT_STRIDE + n] = v.x;
            xt[(k4 * 4 + 1) * XT_STRIDE + n] = v.y;
            xt[(k4 * 4 + 2) * XT_STRIDE + n] = v.z;
            xt[(k4 * 4 + 3) * XT_STRIDE + n] = v.w;
        }
        __syncthreads();

#pragma unroll 4
        for (int k = 0; k < KC; ++k) {
            float4 xa = *(const float4*)(xt + k * XT_STRIDE + tn * 8);
            float4 xb = *(const float4*)(xt + k * XT_STRIDE + tn * 8 + 4);
            ulonglong2 w01 = *(const ulonglong2*)(ws_c + k * DOUT + tc * 8);
            ulonglong2 w23 = *(const ulonglong2*)(ws_c + k * DOUT + tc * 8 + 4);
            float xv[8] = {xa.x, xa.y, xa.z, xa.w, xb.x, xb.y, xb.z, xb.w};
#pragma unroll
            for (int i = 0; i < 8; ++i) {
                unsigned long long x2;
                asm("mov.b64 %0, {%1, %1};" : "=l"(x2) : "f"(xv[i]));
                asm("fma.rn.f32x2 %0, %1, %2, %0;" : "+l"(acc[i][0]) : "l"(x2), "l"(w01.x));
                asm("fma.rn.f32x2 %0, %1, %2, %0;" : "+l"(acc[i][1]) : "l"(x2), "l"(w01.y));
                asm("fma.rn.f32x2 %0, %1, %2, %0;" : "+l"(acc[i][2]) : "l"(x2), "l"(w23.x));
                asm("fma.rn.f32x2 %0, %1, %2, %0;" : "+l"(acc[i][3]) : "l"(x2), "l"(w23.y));
            }
        }
        __syncthreads();
    }

    uint4* zh4 = (uint4*)g_zh;               // 8 uint4 per node row
#pragma unroll
    for (int i = 0; i < 8; ++i) {
        int node = node0 + tn * 8 + i;
        if (node < N_NODES) {
            uint4 o;
            unsigned* op = &o.x;
#pragma unroll
            for (int j = 0; j < 4; ++j) {
                unsigned long long a = acc[i][j];
                float lo = __uint_as_float((unsigned)a);
                float hi = __uint_as_float((unsigned)(a >> 32));
                __half2 h = __floats2half2_rn(lo, hi);
                op[j] = *reinterpret_cast<unsigned*>(&h);
            }
            zh4[(size_t)node * 8 + tc] = o;
        }
    }
}

__global__ void __launch_bounds__(THR)
fill_gemm_kernel(const int* __restrict__ es,
                 const int* __restrict__ ed,
                 const float* __restrict__ x) {
    __shared__ float ws_c[KC * DOUT];        // 4 KB
    __shared__ float xt[KC * XT_STRIDE];     // 8.4 KB
    if (blockIdx.x < GEMM_B) do_gemm(blockIdx.x, x, ws_c, xt);
    else                     do_fill(blockIdx.x - GEMM_B, es, ed);
}

// ---------------------------------------------------------------------------
// Gather on fp16 rows (measured-best shape from R10): 8 lanes per node, lane
// owns one uint4 (8 halves) = one 128B L2 line per edge row. fp32 accumulate,
// unroll-8 MLP. WRITE_HALF: fp16 out (layer 1). RESET: zero counters.
// ---------------------------------------------------------------------------
__device__ __forceinline__ void acc_add(float* acc, uint4 v) {
    const __half2* h = reinterpret_cast<const __half2*>(&v);
#pragma unroll
    for (int j = 0; j < 4; ++j) {
        float2 f = __half22float2(h[j]);
        acc[2 * j]     += f.x;
        acc[2 * j + 1] += f.y;
    }
}

template <bool WRITE_HALF, bool RESET>
__global__ void gather_h_kernel(const uint4* __restrict__ feat_h,
                                void* __restrict__ outp) {
    int t = blockIdx.x * blockDim.x + threadIdx.x;
    int node = t >> 3;                 // four nodes per warp
    int l8   = t & 7;
    if (node >= N_NODES) return;

    int deg = __ldg(&g_cnt[node]);
    if (deg > SLOTS) deg = SLOTS;
    const int* bucket = g_csr_src + (size_t)node * SLOTS;

    float acc[8] = {0.f, 0.f, 0.f, 0.f, 0.f, 0.f, 0.f, 0.f};
    acc_add(acc, __ldg(&feat_h[(size_t)node * 8 + l8]));   // self term

    int i = 0;
    for (; i + 8 <= deg; i += 8) {
        int s[8];
#pragma unroll
        for (int j = 0; j < 8; ++j) s[j] = __ldg(bucket + i + j);
        uint4 v[8];
#pragma unroll
        for (int j = 0; j < 8; ++j) v[j] = __ldg(&feat_h[(size_t)s[j] * 8 + l8]);
#pragma unroll
        for (int j = 0; j < 8; ++j) acc_add(acc, v[j]);
    }
    for (; i < deg; ++i) {
        int s = __ldg(bucket + i);
        acc_add(acc, __ldg(&feat_h[(size_t)s * 8 + l8]));
    }

    if (WRITE_HALF) {
        uint4 o;
        unsigned* op = &o.x;
#pragma unroll
        for (int j = 0; j < 4; ++j) {
            __half2 h = __floats2half2_rn(acc[2 * j], acc[2 * j + 1]);
            op[j] = *reinterpret_cast<unsigned*>(&h);
        }
        ((uint4*)outp)[(size_t)node * 8 + l8] = o;
    } else {
        float4 a = make_float4(acc[0], acc[1], acc[2], acc[3]);
        float4 b = make_float4(acc[4], acc[5], acc[6], acc[7]);
        ((float4*)outp)[(size_t)node * 16 + l8 * 2]     = a;
        ((float4*)outp)[(size_t)node * 16 + l8 * 2 + 1] = b;
    }
    if (RESET && l8 == 0) g_cnt[node] = 0;   // clean for the next call
}

// ---------------------------------------------------------------------------
extern "C" void kernel_launch(void* const* d_in, const int* in_sizes, int n_in,
                              void* d_out, int out_size) {
    const float* x  = (const float*)d_in[0];
    const int*   es = (const int*)d_in[1];
    const int*   ed = (const int*)d_in[2];
    const float* W1 = (const float*)d_in[3];
    const float* W2 = (const float*)d_in[4];
    float*       out = (float*)d_out;

    void *p_zh, *p_z1h;
    cudaGetSymbolAddress(&p_zh,  g_zh);
    cudaGetSymbolAddress(&p_z1h, g_z1h);
    const uint4* zh  = (const uint4*)p_zh;
    uint4*       z1h = (uint4*)p_z1h;

    const int gather_blocks = (N_NODES * 8 + 255) / 256;   // 3125

    prep_kernel<<<DIN, 256>>>(W1, W2);                       // Wf
    fill_gemm_kernel<<<GEMM_B + FILL_B, THR>>>(es, ed, x);   // GEMM ∥ buckets
    gather_h_kernel<true,  false><<<gather_blocks, 256>>>(zh, (void*)z1h);
    gather_h_kernel<false, true ><<<gather_blocks, 256>>>((const uint4*)z1h, (void*)out);
}